// round 14
// baseline (speedup 1.0000x reference)
#include <cuda_runtime.h>
#include <cstdint>

#define Bz    4
#define Cc    64
#define Hh    64
#define Ww    64
#define HW    4096
#define CHW   (Cc*HW)
#define PATCH 9
#define CHUNK 8
#define NCHK  (Cc/CHUNK)            // 8
#define PROW  72                    // smem row: 4 | 64 | 4
#define F2C   (PATCH*PROW)          // 648 floats per staged channel
#define F2BUF (CHUNK*F2C)           // 5184 floats
#define F1BUF (CHUNK*Ww)            // 512 floats
#define SMEM_FLOATS (2*(F2BUF+F1BUF))  // 11392
#define SMEM_BYTES  (SMEM_FLOATS*4)    // 45568
#define NTHR  288                   // 9 warps (warp = dy)
#define NARRIVE 80                  // 72 f2-row + 8 f1 copiers

typedef unsigned long long u64;
union f4u { float4 f; ulonglong2 u; };

// scratch
__device__ float g_inv1[Bz][HW];
__device__ float g_inv2p[Bz][72][72];   // padded inverse norms of f2 (halo = 1.0)

__device__ __forceinline__ uint32_t smem_u32(const void* p) {
    uint32_t a;
    asm("{ .reg .u64 t; cvta.to.shared.u64 t, %1; cvt.u32.u64 %0, t; }" : "=r"(a) : "l"(p));
    return a;
}
__device__ __forceinline__ void bulk_g2s(uint32_t dst, const float* src, uint32_t bytes,
                                         uint32_t mbar) {
    asm volatile("cp.async.bulk.shared::cta.global.mbarrier::complete_tx::bytes "
                 "[%0], [%1], %2, [%3];"
                 :: "r"(dst), "l"(src), "r"(bytes), "r"(mbar) : "memory");
}
__device__ __forceinline__ void mbar_init(uint32_t mbar, uint32_t cnt) {
    asm volatile("mbarrier.init.shared.b64 [%0], %1;" :: "r"(mbar), "r"(cnt) : "memory");
}
__device__ __forceinline__ void mbar_arrive_tx(uint32_t mbar, uint32_t tx) {
    asm volatile("mbarrier.arrive.expect_tx.shared.b64 _, [%0], %1;"
                 :: "r"(mbar), "r"(tx) : "memory");
}
__device__ __forceinline__ void mbar_arrive(uint32_t mbar) {
    asm volatile("mbarrier.arrive.shared.b64 _, [%0];" :: "r"(mbar) : "memory");
}
__device__ __forceinline__ void mbar_wait(uint32_t mbar, uint32_t parity) {
    uint32_t done;
    asm volatile("{\n\t.reg .pred p;\n\t"
                 "mbarrier.try_wait.parity.acquire.cta.shared::cta.b64 p, [%1], %2;\n\t"
                 "selp.b32 %0, 1, 0, p;\n\t}"
                 : "=r"(done) : "r"(mbar), "r"(parity) : "memory");
    if (!done) {
        asm volatile("{\n\t.reg .pred P1;\n\t"
                     "WL_%=:\n\t"
                     "mbarrier.try_wait.parity.acquire.cta.shared::cta.b64 P1, [%0], %1, 0x989680;\n\t"
                     "@P1 bra.uni WD_%=;\n\t"
                     "bra.uni WL_%=;\n\t"
                     "WD_%=:\n\t}"
                     :: "r"(mbar), "r"(parity) : "memory");
    }
}
__device__ __forceinline__ u64 pk(float lo, float hi) {
    u64 r; asm("mov.b64 %0, {%1, %2};" : "=l"(r) : "f"(lo), "f"(hi)); return r;
}
__device__ __forceinline__ void fma2(u64& d, u64 a, u64 b) {
    asm("fma.rn.f32x2 %0, %1, %2, %0;" : "+l"(d) : "l"(a), "l"(b));
}
__device__ __forceinline__ void unpk(u64 p, float& lo, float& hi) {
    asm("mov.b64 {%0, %1}, %2;" : "=f"(lo), "=f"(hi) : "l"(p));
}

// ---------------------------------------------------------------------------
// Kernel 1: inverse L2 norms (R11, fast). 65536 threads (256 CTAs), 8-way
// channel groups, MLP=8, 3-level shfl. Writes flat inv1 + padded inv2 map.
// ---------------------------------------------------------------------------
__global__ void invnorm_kernel(const float* __restrict__ f1,
                               const float* __restrict__ f2) {
    int idx  = blockIdx.x * 256 + threadIdx.x;          // 0..65535
    int cg   = idx & 7;
    int quad = (idx >> 3) & 1023;
    int b    = (idx >> 13) & 3;
    int feat = idx >> 15;
    const float* src = (feat ? f2 : f1) + b * CHW + quad * 4 + cg * 8 * HW;

    float4 s = make_float4(0.f, 0.f, 0.f, 0.f);
#pragma unroll
    for (int i = 0; i < 8; ++i) {
        float4 v = __ldg((const float4*)(src + i * HW));
        s.x += v.x * v.x; s.y += v.y * v.y; s.z += v.z * v.z; s.w += v.w * v.w;
    }
#pragma unroll
    for (int m = 1; m <= 4; m <<= 1) {
        s.x += __shfl_xor_sync(0xffffffffu, s.x, m);
        s.y += __shfl_xor_sync(0xffffffffu, s.y, m);
        s.z += __shfl_xor_sync(0xffffffffu, s.z, m);
        s.w += __shfl_xor_sync(0xffffffffu, s.w, m);
    }
    if (cg == 0) {
        float4 r;
        r.x = rsqrtf(s.x + 1e-6f); r.y = rsqrtf(s.y + 1e-6f);
        r.z = rsqrtf(s.z + 1e-6f); r.w = rsqrtf(s.w + 1e-6f);
        int y = quad >> 4, x = (quad & 15) << 2;
        if (feat == 0) *(float4*)&g_inv1[b][quad * 4] = r;
        else           *(float4*)&g_inv2p[b][y + 4][x + 4] = r;
    }
    if (idx < Bz * 72 * 72) {
        int bb = idx / 5184;
        int rc = idx - bb * 5184;
        int r  = rc / 72, cc = rc - r * 72;
        if (r < 4 || r >= 68 || cc < 4 || cc >= 68)
            g_inv2p[bb][r][cc] = 1.0f;
    }
}

// ---------------------------------------------------------------------------
// Kernel 2: correlation + relu, dx-split for occupancy.
//   grid = [b:4][y:64][dxhalf:2] = 512 CTAs, 288 threads (9 warps = 9 dy).
//   lane = (ch:1)(xq:4): 4 px of row y, half the channels, NDX dx values.
//   3 CTAs/SM (smem 45.5KB, regs<=74) -> ~31 warps/SM.
// ---------------------------------------------------------------------------
template<int DX0, int NDX, int NEVEN, int NODD>
__device__ __forceinline__ void corr_impl(float* smem, uint32_t mb0, uint32_t mb1,
                                          const float* __restrict__ f1,
                                          const float* __restrict__ f2,
                                          float* __restrict__ out) {
    float* s_f2 = smem;                  // [2][CHUNK][PATCH][PROW]
    float* s_f1 = smem + 2 * F2BUF;      // [2][CHUNK][Ww]
    const uint32_t s2 = smem_u32(s_f2);
    const uint32_t s1 = smem_u32(s_f1);

    const int b    = blockIdx.x >> 7;
    const int y    = (blockIdx.x >> 1) & 63;
    const int tid  = threadIdx.x;
    const int dy   = tid >> 5;
    const int lane = tid & 31;
    const int ch   = lane >> 4;                // channel parity
    const int xq   = lane & 15;
    const int x0   = xq << 2;                  // 0..60

    const float* f2b = f2 + b * CHW;
    const float* f1b = f1 + b * CHW + y * Ww;

    // copier geometry (chunk-invariant)
    const int cs = tid / PATCH;                // f2 copier channel (tid<72)
    const int rs = tid - cs * PATCH;           // f2 copier row
    const int rowg = y + rs - 4;
    const bool rvalid = (rowg >= 0) && (rowg < Hh);

    if (tid == 0) { mbar_init(mb0, NARRIVE); mbar_init(mb1, NARRIVE); }

    // one-time zeros: halo cols (288 items) + OOB-row interiors (144 items)
    {
        int i = tid;                            // exactly NTHR
        int buf = i >= 144;
        int t   = i - buf * 144;
        int cr  = t >> 1, side = t & 1;
        int c   = cr / PATCH, r = cr - c * PATCH;
        *(float4*)&s_f2[buf * F2BUF + (c * PATCH + r) * PROW + side * 68] =
            make_float4(0.f, 0.f, 0.f, 0.f);
    }
    if (tid < 144) {
        int buf = tid >= 72;
        int cr  = tid - buf * 72;
        int c   = cr / PATCH, r = cr - c * PATCH;
        int row = y + r - 4;
        if (row < 0 || row >= Hh) {
            float4 z = make_float4(0.f, 0.f, 0.f, 0.f);
            float* rowp = &s_f2[buf * F2BUF + (c * PATCH + r) * PROW + 4];
#pragma unroll
            for (int q = 0; q < 16; ++q) *(float4*)&rowp[q * 4] = z;
        }
    }
    __syncthreads();

    auto stage = [&](int c0, int sel) {
        uint32_t mb = sel ? mb1 : mb0;
        if (tid < CHUNK * PATCH) {              // 72 f2-row copiers, 256B
            if (rvalid) {
                mbar_arrive_tx(mb, Ww * 4);
                bulk_g2s(s2 + (uint32_t)((sel * F2BUF + (cs * PATCH + rs) * PROW + 4) * 4),
                         f2b + (c0 + cs) * HW + rowg * Ww, Ww * 4, mb);
            } else {
                mbar_arrive(mb);
            }
        } else if (tid < NARRIVE) {             // 8 f1 copiers, 256B
            int c = tid - CHUNK * PATCH;
            mbar_arrive_tx(mb, Ww * 4);
            bulk_g2s(s1 + (uint32_t)((sel * F1BUF + c * Ww) * 4),
                     f1b + (c0 + c) * HW, Ww * 4, mb);
        }
    };

    // accumulators for this half
    u64 eacc[NEVEN][2];
    u64 macc[NODD];
    float s0a[NODD], s3a[NODD];
#pragma unroll
    for (int e = 0; e < NEVEN; ++e) { eacc[e][0] = 0ull; eacc[e][1] = 0ull; }
#pragma unroll
    for (int o = 0; o < NODD; ++o) { macc[o] = 0ull; s0a[o] = 0.f; s3a[o] = 0.f; }

    stage(0, 0);
    stage(CHUNK, 1);

#pragma unroll 1
    for (int k = 0; k < NCHK; ++k) {
        mbar_wait(k & 1 ? mb1 : mb0, (k >> 1) & 1);

        const float* sbuf = s_f2 + (k & 1) * F2BUF + dy * PROW + x0;
        const float* abuf = s_f1 + (k & 1) * F1BUF + x0;
#pragma unroll
        for (int i = 0; i < CHUNK / 2; ++i) {
            const int c = (i << 1) + ch;
            const float* s = sbuf + c * F2C;
            f4u va, vb, af;
            // half0 uses cols 0..7 (v0,v1); half1 uses cols 4..11 (v1,v2)
            va.f = *(const float4*)(s + ((DX0 == 0) ? 0 : 4));
            vb.f = *(const float4*)(s + ((DX0 == 0) ? 4 : 8));
            af.f = *(const float4*)(abuf + c * Ww);

            const u64 a01 = af.u.x;
            const u64 a23 = af.u.y;
            const u64 am  = pk(af.f.y, af.f.z);     // the ONE pack

            if (DX0 == 0) {
                // even dx 0,2,4: w0..w3 = (va.lo, va.hi, vb.lo, vb.hi)
                fma2(eacc[0][0], a01, va.u.x); fma2(eacc[0][1], a23, va.u.y);
                fma2(eacc[1][0], a01, va.u.y); fma2(eacc[1][1], a23, vb.u.x);
                fma2(eacc[2][0], a01, vb.u.x); fma2(eacc[2][1], a23, vb.u.y);
                // odd dx 1,3
                fma2(macc[0], am, va.u.y);
                fma2(macc[1], am, vb.u.x);
                s0a[0] = fmaf(af.f.x, va.f.y, s0a[0]);   // v[1]
                s0a[1] = fmaf(af.f.x, va.f.w, s0a[1]);   // v[3]
                s3a[0] = fmaf(af.f.w, vb.f.x, s3a[0]);   // v[4]
                s3a[1] = fmaf(af.f.w, vb.f.z, s3a[1]);   // v[6]
            } else {
                // va = cols 4..7 (w2',w3'), vb = cols 8..11 (w4',w5')
                // even dx 6,8
                fma2(eacc[0][0], a01, va.u.y); fma2(eacc[0][1], a23, vb.u.x); // dx6
                fma2(eacc[1][0], a01, vb.u.x); fma2(eacc[1][1], a23, vb.u.y); // dx8
                // odd dx 5,7
                fma2(macc[0], am, va.u.y);               // (v6,v7)
                fma2(macc[1], am, vb.u.x);               // (v8,v9)
                s0a[0] = fmaf(af.f.x, va.f.y, s0a[0]);   // v[5]
                s0a[1] = fmaf(af.f.x, va.f.w, s0a[1]);   // v[7]
                s3a[0] = fmaf(af.f.w, vb.f.x, s3a[0]);   // v[8]
                s3a[1] = fmaf(af.f.w, vb.f.z, s3a[1]);   // v[10]
            }
        }
        if (k + 2 < NCHK) {
            __syncthreads();
            stage((k + 2) * CHUNK, k & 1);
        }
    }

    // ---- assemble per-dx results (local d = 0..NDX-1, global dx = DX0+d)
    float a[NDX][4];
    if (DX0 == 0) {
        unpk(eacc[0][0], a[0][0], a[0][1]); unpk(eacc[0][1], a[0][2], a[0][3]);
        unpk(eacc[1][0], a[2][0], a[2][1]); unpk(eacc[1][1], a[2][2], a[2][3]);
        unpk(eacc[2][0], a[4][0], a[4][1]); unpk(eacc[2][1], a[4][2], a[4][3]);
        a[1][0] = s0a[0]; unpk(macc[0], a[1][1], a[1][2]); a[1][3] = s3a[0];
        a[3][0] = s0a[1]; unpk(macc[1], a[3][1], a[3][2]); a[3][3] = s3a[1];
    } else {
        // local order: d0=dx5(odd), d1=dx6(even), d2=dx7(odd), d3=dx8(even)
        a[0][0] = s0a[0]; unpk(macc[0], a[0][1], a[0][2]); a[0][3] = s3a[0];
        unpk(eacc[0][0], a[1][0], a[1][1]); unpk(eacc[0][1], a[1][2], a[1][3]);
        a[2][0] = s0a[1]; unpk(macc[1], a[2][1], a[2][2]); a[2][3] = s3a[1];
        unpk(eacc[1][0], a[3][0], a[3][1]); unpk(eacc[1][1], a[3][2], a[3][3]);
    }

    // ---- combine channel halves in-warp (partner lane = xor 16)
#pragma unroll
    for (int d = 0; d < NDX; ++d)
#pragma unroll
        for (int j = 0; j < 4; ++j)
            a[d][j] += __shfl_xor_sync(0xffffffffu, a[d][j], 16);

    if (ch == 0) {
        constexpr int VOFF = (DX0 == 0) ? 0 : 4;
        float4 iv1 = *(const float4*)(&g_inv1[b][y * Ww + x0]);
        float e[8];
        *(float4*)&e[0] = *(const float4*)(&g_inv2p[b][y + dy][x0 + VOFF]);
        *(float4*)&e[4] = *(const float4*)(&g_inv2p[b][y + dy][x0 + VOFF + 4]);

        float* op = out + (size_t)(b * 81 + dy * PATCH + DX0) * HW + y * Ww + x0;
#pragma unroll
        for (int d = 0; d < NDX; ++d) {
            const int j = DX0 + d - VOFF;
            float4 o;
            o.x = fmaxf(a[d][0] * iv1.x * e[j + 0], 0.f);
            o.y = fmaxf(a[d][1] * iv1.y * e[j + 1], 0.f);
            o.z = fmaxf(a[d][2] * iv1.z * e[j + 2], 0.f);
            o.w = fmaxf(a[d][3] * iv1.w * e[j + 3], 0.f);
            *(float4*)(op + d * HW) = o;
        }
    }
}

__global__ __launch_bounds__(NTHR, 3)
void corr_kernel(const float* __restrict__ f1,
                 const float* __restrict__ f2,
                 float* __restrict__ out) {
    extern __shared__ float smem[];
    __shared__ u64 s_mbar[2];
    uint32_t mb0 = smem_u32(&s_mbar[0]);
    uint32_t mb1 = smem_u32(&s_mbar[1]);
    if (blockIdx.x & 1) corr_impl<5, 4, 2, 2>(smem, mb0, mb1, f1, f2, out);
    else                corr_impl<0, 5, 3, 2>(smem, mb0, mb1, f1, f2, out);
}

// ---------------------------------------------------------------------------
extern "C" void kernel_launch(void* const* d_in, const int* in_sizes, int n_in,
                              void* d_out, int out_size) {
    const float* f1 = (const float*)d_in[0];
    const float* f2 = (const float*)d_in[1];
    float* out = (float*)d_out;

    cudaFuncSetAttribute(corr_kernel,
                         cudaFuncAttributeMaxDynamicSharedMemorySize, SMEM_BYTES);

    invnorm_kernel<<<256, 256>>>(f1, f2);
    corr_kernel<<<Bz * Hh * 2, NTHR, SMEM_BYTES>>>(f1, f2, out);
}

// round 15
// speedup vs baseline: 1.5389x; 1.5389x over previous
#include <cuda_runtime.h>
#include <cstdint>

#define Bz    4
#define Cc    64
#define Hh    64
#define Ww    64
#define HW    4096
#define CHW   (Cc*HW)
#define PATCH 9
#define PROW  72
#define PSIZE (PROW*PROW)           // 5184 floats per padded channel plane
#define NTHR  288                   // 9 warps (warp = dy)

typedef unsigned long long u64;
union f4u { float4 f; ulonglong2 u; };

// scratch
__device__ float g_inv1[Bz][HW];
__device__ float g_inv2p[Bz][72][72];     // padded inverse norms of f2 (halo=1)
__device__ float g_f2p[Bz][Cc][72][72];   // padded RAW f2 (zero halos)

__device__ __forceinline__ u64 pk(float lo, float hi) {
    u64 r; asm("mov.b64 %0, {%1, %2};" : "=l"(r) : "f"(lo), "f"(hi)); return r;
}
__device__ __forceinline__ void fma2(u64& d, u64 a, u64 b) {
    asm("fma.rn.f32x2 %0, %1, %2, %0;" : "+l"(d) : "l"(a), "l"(b));
}
__device__ __forceinline__ void unpk(u64 p, float& lo, float& hi) {
    asm("mov.b64 {%0, %1}, %2;" : "=f"(lo), "=f"(hi) : "l"(p));
}

// ---------------------------------------------------------------------------
// Kernel 1: inverse L2 norms. 65536 threads (256 CTAs), 8-way channel groups,
// MLP=8, 3-level shfl. Writes flat inv1 + padded inv2 map (+halo).
// ---------------------------------------------------------------------------
__global__ void invnorm_kernel(const float* __restrict__ f1,
                               const float* __restrict__ f2) {
    int idx  = blockIdx.x * 256 + threadIdx.x;          // 0..65535
    int cg   = idx & 7;
    int quad = (idx >> 3) & 1023;
    int b    = (idx >> 13) & 3;
    int feat = idx >> 15;
    const float* src = (feat ? f2 : f1) + b * CHW + quad * 4 + cg * 8 * HW;

    float4 s = make_float4(0.f, 0.f, 0.f, 0.f);
#pragma unroll
    for (int i = 0; i < 8; ++i) {
        float4 v = __ldg((const float4*)(src + i * HW));
        s.x += v.x * v.x; s.y += v.y * v.y; s.z += v.z * v.z; s.w += v.w * v.w;
    }
#pragma unroll
    for (int m = 1; m <= 4; m <<= 1) {
        s.x += __shfl_xor_sync(0xffffffffu, s.x, m);
        s.y += __shfl_xor_sync(0xffffffffu, s.y, m);
        s.z += __shfl_xor_sync(0xffffffffu, s.z, m);
        s.w += __shfl_xor_sync(0xffffffffu, s.w, m);
    }
    if (cg == 0) {
        float4 r;
        r.x = rsqrtf(s.x + 1e-6f); r.y = rsqrtf(s.y + 1e-6f);
        r.z = rsqrtf(s.z + 1e-6f); r.w = rsqrtf(s.w + 1e-6f);
        int y = quad >> 4, x = (quad & 15) << 2;
        if (feat == 0) *(float4*)&g_inv1[b][quad * 4] = r;
        else           *(float4*)&g_inv2p[b][y + 4][x + 4] = r;
    }
    if (idx < Bz * 72 * 72) {
        int bb = idx / 5184;
        int rc = idx - bb * 5184;
        int r  = rc / 72, cc = rc - r * 72;
        if (r < 4 || r >= 68 || cc < 4 || cc >= 68)
            g_inv2p[bb][r][cc] = 1.0f;
    }
}

// ---------------------------------------------------------------------------
// Kernel 2: pad raw f2 into g_f2p (zero halos). Coalesced R/W.
//   Bz*Cc*72*18 = 331776 quads -> 1296 blocks x 256.
// ---------------------------------------------------------------------------
__global__ void padraw_kernel(const float* __restrict__ f2) {
    int idx = blockIdx.x * 256 + threadIdx.x;
    int xq  = idx % 18;
    int t   = idx / 18;
    int r   = t % 72;  t /= 72;
    int c   = t & 63;
    int b   = t >> 6;
    int y   = r - 4;
    float4 val = make_float4(0.f, 0.f, 0.f, 0.f);
    if (y >= 0 && y < Hh && xq >= 1 && xq <= 16) {
        val = __ldg((const float4*)(f2 + (b * Cc + c) * HW + y * Ww + (xq - 1) * 4));
    }
    *(float4*)&g_f2p[b][c][r][xq * 4] = val;
}

// ---------------------------------------------------------------------------
// Kernel 3: correlation + relu — NO smem, NO barriers, pure LDG compute.
//   grid = [b:4][y:64] = 256 CTAs, 288 threads (9 warps = 9 dy).
//   lane = (ch:1)(xq:4): 4 px of row y, half the channels, all 9 dx.
//   Per channel: 3 LDG.128 (padded f2 window, no predication) + 1 LDG.128 f1
//   + 27-slot FFMA2 block. Channel halves combined in-warp via shfl_xor(16).
// ---------------------------------------------------------------------------
__global__ __launch_bounds__(NTHR, 2)
void corr_kernel(const float* __restrict__ f1, float* __restrict__ out) {
    const int b    = blockIdx.x >> 6;
    const int y    = blockIdx.x & 63;
    const int tid  = threadIdx.x;
    const int dy   = tid >> 5;                 // warp = dy (0..8)
    const int lane = tid & 31;
    const int ch   = lane >> 4;                // channel parity
    const int xq   = lane & 15;                // x quad
    const int x0   = xq << 2;

    // padded row y+dy, padded col x0 == orig (y+dy-4, x0-4): window v[0..11]
    const float* f2c = &g_f2p[b][ch][y + dy][x0];       // +2*PSIZE per step
    const float* f1c = f1 + b * CHW + ch * HW + y * Ww + x0;  // +2*HW per step

    u64 eacc[5][2];
    u64 macc[4];
    float s0a[4], s3a[4];
#pragma unroll
    for (int e = 0; e < 5; ++e) { eacc[e][0] = 0ull; eacc[e][1] = 0ull; }
#pragma unroll
    for (int o = 0; o < 4; ++o) { macc[o] = 0ull; s0a[o] = 0.f; s3a[o] = 0.f; }

#pragma unroll 8
    for (int i = 0; i < Cc / 2; ++i) {
        f4u v0, v1, v2, af;
        v0.f = __ldg((const float4*)(f2c + i * (2 * PSIZE)));
        v1.f = __ldg((const float4*)(f2c + i * (2 * PSIZE) + 4));
        v2.f = __ldg((const float4*)(f2c + i * (2 * PSIZE) + 8));
        af.f = __ldg((const float4*)(f1c + i * (2 * HW)));

        const u64 a01 = af.u.x;
        const u64 a23 = af.u.y;
        const u64 am  = pk(af.f.y, af.f.z);     // the ONE pack

        // even dx = 2e
        fma2(eacc[0][0], a01, v0.u.x); fma2(eacc[0][1], a23, v0.u.y);
        fma2(eacc[1][0], a01, v0.u.y); fma2(eacc[1][1], a23, v1.u.x);
        fma2(eacc[2][0], a01, v1.u.x); fma2(eacc[2][1], a23, v1.u.y);
        fma2(eacc[3][0], a01, v1.u.y); fma2(eacc[3][1], a23, v2.u.x);
        fma2(eacc[4][0], a01, v2.u.x); fma2(eacc[4][1], a23, v2.u.y);

        // odd dx = 2o+1: middle pair (px1,px2) + scalars px0/px3
        fma2(macc[0], am, v0.u.y);
        fma2(macc[1], am, v1.u.x);
        fma2(macc[2], am, v1.u.y);
        fma2(macc[3], am, v2.u.x);
        s0a[0] = fmaf(af.f.x, v0.f.y, s0a[0]);
        s0a[1] = fmaf(af.f.x, v0.f.w, s0a[1]);
        s0a[2] = fmaf(af.f.x, v1.f.y, s0a[2]);
        s0a[3] = fmaf(af.f.x, v1.f.w, s0a[3]);
        s3a[0] = fmaf(af.f.w, v1.f.x, s3a[0]);
        s3a[1] = fmaf(af.f.w, v1.f.z, s3a[1]);
        s3a[2] = fmaf(af.f.w, v2.f.x, s3a[2]);
        s3a[3] = fmaf(af.f.w, v2.f.z, s3a[3]);
    }

    // ---- assemble per-dx results
    float a[PATCH][4];
#pragma unroll
    for (int e = 0; e < 5; ++e) {
        unpk(eacc[e][0], a[2 * e][0], a[2 * e][1]);
        unpk(eacc[e][1], a[2 * e][2], a[2 * e][3]);
    }
#pragma unroll
    for (int o = 0; o < 4; ++o) {
        a[2 * o + 1][0] = s0a[o];
        unpk(macc[o], a[2 * o + 1][1], a[2 * o + 1][2]);
        a[2 * o + 1][3] = s3a[o];
    }

    // ---- combine channel halves in-warp (partner lane = xor 16)
#pragma unroll
    for (int d = 0; d < PATCH; ++d)
#pragma unroll
        for (int j = 0; j < 4; ++j)
            a[d][j] += __shfl_xor_sync(0xffffffffu, a[d][j], 16);

    if (ch == 0) {
        float4 iv1 = *(const float4*)(&g_inv1[b][y * Ww + x0]);
        float e[12];
        *(float4*)&e[0] = *(const float4*)(&g_inv2p[b][y + dy][x0]);
        *(float4*)&e[4] = *(const float4*)(&g_inv2p[b][y + dy][x0 + 4]);
        *(float4*)&e[8] = *(const float4*)(&g_inv2p[b][y + dy][x0 + 8]);

        float* op = out + (size_t)(b * 81 + dy * PATCH) * HW + y * Ww + x0;
#pragma unroll
        for (int d = 0; d < PATCH; ++d) {
            float4 o;
            o.x = fmaxf(a[d][0] * iv1.x * e[d + 0], 0.f);
            o.y = fmaxf(a[d][1] * iv1.y * e[d + 1], 0.f);
            o.z = fmaxf(a[d][2] * iv1.z * e[d + 2], 0.f);
            o.w = fmaxf(a[d][3] * iv1.w * e[d + 3], 0.f);
            *(float4*)(op + d * HW) = o;
        }
    }
}

// ---------------------------------------------------------------------------
extern "C" void kernel_launch(void* const* d_in, const int* in_sizes, int n_in,
                              void* d_out, int out_size) {
    const float* f1 = (const float*)d_in[0];
    const float* f2 = (const float*)d_in[1];
    float* out = (float*)d_out;

    invnorm_kernel<<<256, 256>>>(f1, f2);
    padraw_kernel<<<1296, 256>>>(f2);
    corr_kernel<<<Bz * Hh, NTHR>>>(f1, out);
}

// round 16
// speedup vs baseline: 1.7287x; 1.1233x over previous
#include <cuda_runtime.h>
#include <cstdint>

#define Bz    4
#define Cc    64
#define Hh    64
#define Ww    64
#define HW    4096
#define CHW   (Cc*HW)
#define PATCH 9
#define PROW  72
#define PSIZE (PROW*PROW)           // 5184 floats per padded channel plane
#define NTHR  288                   // 9 warps (warp = dy)
#define PAD_BLOCKS 1296             // Bz*Cc*72*18 / 256
#define NORM_BLOCKS 64              // 16384 threads
#define AUX_BLOCKS (PAD_BLOCKS + NORM_BLOCKS)

typedef unsigned long long u64;
union f4u { float4 f; ulonglong2 u; };

// scratch
__device__ float g_inv1[Bz][HW];
__device__ float g_inv2p[Bz][72][72];     // padded inverse norms of f2 (halo=1)
__device__ float g_f2p[Bz][Cc][72][72];   // padded RAW f2 (zero halos)

__device__ __forceinline__ u64 pk(float lo, float hi) {
    u64 r; asm("mov.b64 %0, {%1, %2};" : "=l"(r) : "f"(lo), "f"(hi)); return r;
}
__device__ __forceinline__ void fma2(u64& d, u64 a, u64 b) {
    asm("fma.rn.f32x2 %0, %1, %2, %0;" : "+l"(d) : "l"(a), "l"(b));
}
__device__ __forceinline__ void unpk(u64 p, float& lo, float& hi) {
    asm("mov.b64 {%0, %1}, %2;" : "=f"(lo), "=f"(hi) : "l"(p));
}

// ---------------------------------------------------------------------------
// Kernel 1 (fused aux):
//   blocks [0, 1296): pad raw f2 into g_f2p (zero halos) + write inv2p halo.
//   blocks [1296, 1360): inverse L2 norms, coalesced lane layout.
//     thread = (feat:1)(b:2)(quadhi:6)(cg:1)(quadlo:4); warp-load = two
//     contiguous 256B segments; 32 channels/thread; shfl_xor(16) combine.
// ---------------------------------------------------------------------------
__global__ void aux_kernel(const float* __restrict__ f1,
                           const float* __restrict__ f2) {
    if (blockIdx.x < PAD_BLOCKS) {
        int idx = blockIdx.x * 256 + threadIdx.x;
        int xq  = idx % 18;
        int t   = idx / 18;
        int r   = t % 72;  t /= 72;
        int c   = t & 63;
        int b   = t >> 6;
        int y   = r - 4;
        float4 val = make_float4(0.f, 0.f, 0.f, 0.f);
        if (y >= 0 && y < Hh && xq >= 1 && xq <= 16) {
            val = __ldg((const float4*)(f2 + (b * Cc + c) * HW + y * Ww + (xq - 1) * 4));
        }
        *(float4*)&g_f2p[b][c][r][xq * 4] = val;

        // inv2p halo (value irrelevant: padded f2 is 0 there)
        if (idx < Bz * 72 * 72) {
            int bb = idx / 5184;
            int rc = idx - bb * 5184;
            int rr = rc / 72, cc = rc - rr * 72;
            if (rr < 4 || rr >= 68 || cc < 4 || cc >= 68)
                g_inv2p[bb][rr][cc] = 1.0f;
        }
    } else {
        int j      = (blockIdx.x - PAD_BLOCKS) * 256 + threadIdx.x;  // 0..16383
        int quadlo = j & 15;
        int cg     = (j >> 4) & 1;
        int quadhi = (j >> 5) & 63;
        int b      = (j >> 11) & 3;
        int feat   = (j >> 13) & 1;
        int quad   = quadhi * 16 + quadlo;
        const float* src = (feat ? f2 : f1) + b * CHW + quad * 4 + cg * 32 * HW;

        float4 s = make_float4(0.f, 0.f, 0.f, 0.f);
#pragma unroll
        for (int i = 0; i < 32; ++i) {
            float4 v = __ldg((const float4*)(src + i * HW));
            s.x += v.x * v.x; s.y += v.y * v.y; s.z += v.z * v.z; s.w += v.w * v.w;
        }
        s.x += __shfl_xor_sync(0xffffffffu, s.x, 16);
        s.y += __shfl_xor_sync(0xffffffffu, s.y, 16);
        s.z += __shfl_xor_sync(0xffffffffu, s.z, 16);
        s.w += __shfl_xor_sync(0xffffffffu, s.w, 16);

        if (cg == 0) {
            float4 r;
            r.x = rsqrtf(s.x + 1e-6f); r.y = rsqrtf(s.y + 1e-6f);
            r.z = rsqrtf(s.z + 1e-6f); r.w = rsqrtf(s.w + 1e-6f);
            int y = quad >> 4, x = (quad & 15) << 2;
            if (feat == 0) *(float4*)&g_inv1[b][quad * 4] = r;
            else           *(float4*)&g_inv2p[b][y + 4][x + 4] = r;
        }
    }
}

// ---------------------------------------------------------------------------
// Kernel 2: correlation + relu — NO smem, NO barriers, pure LDG compute.
//   (R15 winner, unchanged.)
//   grid = [b:4][y:64] = 256 CTAs, 288 threads (9 warps = 9 dy).
//   lane = (ch:1)(xq:4): 4 px of row y, half the channels, all 9 dx.
// ---------------------------------------------------------------------------
__global__ __launch_bounds__(NTHR, 2)
void corr_kernel(const float* __restrict__ f1, float* __restrict__ out) {
    const int b    = blockIdx.x >> 6;
    const int y    = blockIdx.x & 63;
    const int tid  = threadIdx.x;
    const int dy   = tid >> 5;                 // warp = dy (0..8)
    const int lane = tid & 31;
    const int ch   = lane >> 4;                // channel parity
    const int xq   = lane & 15;                // x quad
    const int x0   = xq << 2;

    const float* f2c = &g_f2p[b][ch][y + dy][x0];
    const float* f1c = f1 + b * CHW + ch * HW + y * Ww + x0;

    u64 eacc[5][2];
    u64 macc[4];
    float s0a[4], s3a[4];
#pragma unroll
    for (int e = 0; e < 5; ++e) { eacc[e][0] = 0ull; eacc[e][1] = 0ull; }
#pragma unroll
    for (int o = 0; o < 4; ++o) { macc[o] = 0ull; s0a[o] = 0.f; s3a[o] = 0.f; }

#pragma unroll 8
    for (int i = 0; i < Cc / 2; ++i) {
        f4u v0, v1, v2, af;
        v0.f = __ldg((const float4*)(f2c + i * (2 * PSIZE)));
        v1.f = __ldg((const float4*)(f2c + i * (2 * PSIZE) + 4));
        v2.f = __ldg((const float4*)(f2c + i * (2 * PSIZE) + 8));
        af.f = __ldg((const float4*)(f1c + i * (2 * HW)));

        const u64 a01 = af.u.x;
        const u64 a23 = af.u.y;
        const u64 am  = pk(af.f.y, af.f.z);     // the ONE pack

        fma2(eacc[0][0], a01, v0.u.x); fma2(eacc[0][1], a23, v0.u.y);
        fma2(eacc[1][0], a01, v0.u.y); fma2(eacc[1][1], a23, v1.u.x);
        fma2(eacc[2][0], a01, v1.u.x); fma2(eacc[2][1], a23, v1.u.y);
        fma2(eacc[3][0], a01, v1.u.y); fma2(eacc[3][1], a23, v2.u.x);
        fma2(eacc[4][0], a01, v2.u.x); fma2(eacc[4][1], a23, v2.u.y);

        fma2(macc[0], am, v0.u.y);
        fma2(macc[1], am, v1.u.x);
        fma2(macc[2], am, v1.u.y);
        fma2(macc[3], am, v2.u.x);
        s0a[0] = fmaf(af.f.x, v0.f.y, s0a[0]);
        s0a[1] = fmaf(af.f.x, v0.f.w, s0a[1]);
        s0a[2] = fmaf(af.f.x, v1.f.y, s0a[2]);
        s0a[3] = fmaf(af.f.x, v1.f.w, s0a[3]);
        s3a[0] = fmaf(af.f.w, v1.f.x, s3a[0]);
        s3a[1] = fmaf(af.f.w, v1.f.z, s3a[1]);
        s3a[2] = fmaf(af.f.w, v2.f.x, s3a[2]);
        s3a[3] = fmaf(af.f.w, v2.f.z, s3a[3]);
    }

    // ---- assemble per-dx results
    float a[PATCH][4];
#pragma unroll
    for (int e = 0; e < 5; ++e) {
        unpk(eacc[e][0], a[2 * e][0], a[2 * e][1]);
        unpk(eacc[e][1], a[2 * e][2], a[2 * e][3]);
    }
#pragma unroll
    for (int o = 0; o < 4; ++o) {
        a[2 * o + 1][0] = s0a[o];
        unpk(macc[o], a[2 * o + 1][1], a[2 * o + 1][2]);
        a[2 * o + 1][3] = s3a[o];
    }

    // ---- combine channel halves in-warp (partner lane = xor 16)
#pragma unroll
    for (int d = 0; d < PATCH; ++d)
#pragma unroll
        for (int j = 0; j < 4; ++j)
            a[d][j] += __shfl_xor_sync(0xffffffffu, a[d][j], 16);

    if (ch == 0) {
        float4 iv1 = *(const float4*)(&g_inv1[b][y * Ww + x0]);
        float e[12];
        *(float4*)&e[0] = *(const float4*)(&g_inv2p[b][y + dy][x0]);
        *(float4*)&e[4] = *(const float4*)(&g_inv2p[b][y + dy][x0 + 4]);
        *(float4*)&e[8] = *(const float4*)(&g_inv2p[b][y + dy][x0 + 8]);

        float* op = out + (size_t)(b * 81 + dy * PATCH) * HW + y * Ww + x0;
#pragma unroll
        for (int d = 0; d < PATCH; ++d) {
            float4 o;
            o.x = fmaxf(a[d][0] * iv1.x * e[d + 0], 0.f);
            o.y = fmaxf(a[d][1] * iv1.y * e[d + 1], 0.f);
            o.z = fmaxf(a[d][2] * iv1.z * e[d + 2], 0.f);
            o.w = fmaxf(a[d][3] * iv1.w * e[d + 3], 0.f);
            *(float4*)(op + d * HW) = o;
        }
    }
}

// ---------------------------------------------------------------------------
extern "C" void kernel_launch(void* const* d_in, const int* in_sizes, int n_in,
                              void* d_out, int out_size) {
    const float* f1 = (const float*)d_in[0];
    const float* f2 = (const float*)d_in[1];
    float* out = (float*)d_out;

    aux_kernel<<<AUX_BLOCKS, 256>>>(f1, f2);
    corr_kernel<<<Bz * Hh, NTHR>>>(f1, out);
}